// round 14
// baseline (speedup 1.0000x reference)
#include <cuda_runtime.h>

// DenseCRFLoss on GB300 — R8: p-pair f32x2 packing (q broadcast from smem),
// ~40 regs -> 6 blocks/SM (75% occ), QSPLIT=8, fused finalize.
//
// loss = -(1/N) * sum_{n,k,p,q} S[n,k,p] * exp(-0.5*||f_p - f_q||^2) * S[n,k,q]
// out  = WEIGHT * loss, WEIGHT = 2e-9, N = 4.
// K_pq = exp2( f'_p . f'_q + h'_p + h'_q ).  Symmetry: diag + 2*strict-upper.
// s0+s1=1: w = a_p*s0q + b_p, a=2s0p-1, b=1-s0p -> split accumulators.

#define N_IMG   4
#define P       4096
#define TS      512             // tile side (p's per block = THREADS p-pairs *2)
#define NT      8               // P / TS
#define NTRI    36              // upper-tri tiles
#define QSPLIT  8               // q-chunks per tile
#define QC      (TS / QSPLIT)   // 64 q's per block
#define NBLOCKS (N_IMG * NTRI * QSPLIT)  // 1152
#define THREADS 256

typedef unsigned long long u64;

__device__ u64   g_qrec[N_IMG * P * 8];         // per-q duplicated comps, 64B/q
__device__ u64   g_prec[N_IMG * (P / 2) * 8];   // per-p-pair packed comps, 64B/pair
__device__ float g_partial[NBLOCKS];
__device__ unsigned int g_count;                // zero-init; reset each run

__device__ __forceinline__ float ex2f(float x) {
    float r; asm("ex2.approx.f32 %0, %1;" : "=f"(r) : "f"(x)); return r;
}
__device__ __forceinline__ u64 fma2(u64 a, u64 b, u64 c) {
    u64 d; asm("fma.rn.f32x2 %0, %1, %2, %3;" : "=l"(d) : "l"(a), "l"(b), "l"(c)); return d;
}
__device__ __forceinline__ u64 add2(u64 a, u64 b) {
    u64 d; asm("add.rn.f32x2 %0, %1, %2;" : "=l"(d) : "l"(a), "l"(b)); return d;
}
__device__ __forceinline__ u64 mul2(u64 a, u64 b) {
    u64 d; asm("mul.rn.f32x2 %0, %1, %2;" : "=l"(d) : "l"(a), "l"(b)); return d;
}
__device__ __forceinline__ u64 pack2(float lo, float hi) {
    u64 d; asm("mov.b64 %0, {%1, %2};" : "=l"(d) : "f"(lo), "f"(hi)); return d;
}
__device__ __forceinline__ float2 unpack2(u64 v) {
    float2 r; asm("mov.b64 {%0, %1}, %2;" : "=f"(r.x), "=f"(r.y) : "l"(v)); return r;
}

// Feature for pixel pix of image n: f[0..4] scaled features, f[5]=h', f[6]=s0.
__device__ __forceinline__ void feat(const float* __restrict__ img,
                                     const float* __restrict__ seg,
                                     int n, int pix, float f[7]) {
    const float LOG2E = 1.44269504088896340736f;
    const float SQ    = 1.20112240878644981f;   // sqrt(LOG2E)
    int y = pix >> 6, x = pix & 63;
    int o = (2 * y) * 128 + 2 * x;

    const float* ib = img + (size_t)n * 3 * 16384;
    float r = ib[o];
    float g = ib[16384 + o];
    float b = ib[32768 + o];

    float f0 = (float)x * (1.0f / 50.0f);   // SIGMA_XY * SCALE = 50
    float f1 = (float)y * (1.0f / 50.0f);
    float f2 = r * (1.0f / 15.0f);          // SIGMA_RGB = 15
    float f3 = g * (1.0f / 15.0f);
    float f4 = b * (1.0f / 15.0f);
    float h = -0.5f * LOG2E * (f0*f0 + f1*f1 + f2*f2 + f3*f3 + f4*f4);

    const float* sb = seg + (size_t)n * 2 * 16384;
    float s0 = 0.25f * (sb[o] + sb[o+1] + sb[o+128] + sb[o+129]);

    f[0] = f0 * SQ; f[1] = f1 * SQ; f[2] = f2 * SQ; f[3] = f3 * SQ; f[4] = f4 * SQ;
    f[5] = h;       f[6] = s0;
}

// ---------------------------------------------------------------------------
// Prep: one thread per pixel-PAIR. Writes 2 duplicated q-records + 1 packed
// p-pair record.
// ---------------------------------------------------------------------------
__global__ void __launch_bounds__(256)
crf_prep(const float* __restrict__ img, const float* __restrict__ seg) {
    int pr = blockIdx.x * blockDim.x + threadIdx.x;
    if (pr >= N_IMG * (P / 2)) return;
    int n = pr / (P / 2);
    int r = pr % (P / 2);

    float fA[7], fB[7];
    feat(img, seg, n, 2 * r,     fA);
    feat(img, seg, n, 2 * r + 1, fB);

    // q-records: each component duplicated {c,c}; layout per q (8 u64):
    // [{f0},{f1},{f2},{f3},{f4},{h},{s0},{pad}]
    float4* qA = reinterpret_cast<float4*>(&g_qrec[(size_t)(n * P + 2 * r) * 8]);
    qA[0] = make_float4(fA[0], fA[0], fA[1], fA[1]);
    qA[1] = make_float4(fA[2], fA[2], fA[3], fA[3]);
    qA[2] = make_float4(fA[4], fA[4], fA[5], fA[5]);
    qA[3] = make_float4(fA[6], fA[6], 0.0f, 0.0f);
    float4* qB = reinterpret_cast<float4*>(&g_qrec[(size_t)(n * P + 2 * r + 1) * 8]);
    qB[0] = make_float4(fB[0], fB[0], fB[1], fB[1]);
    qB[1] = make_float4(fB[2], fB[2], fB[3], fB[3]);
    qB[2] = make_float4(fB[4], fB[4], fB[5], fB[5]);
    qB[3] = make_float4(fB[6], fB[6], 0.0f, 0.0f);

    // p-pair record: components packed {A,B}; layout (8 u64):
    // [{f0},{f1},{f2},{f3},{f4},{h},{a},{b}]
    float4* pp = reinterpret_cast<float4*>(&g_prec[(size_t)pr * 8]);
    pp[0] = make_float4(fA[0], fB[0], fA[1], fB[1]);
    pp[1] = make_float4(fA[2], fB[2], fA[3], fB[3]);
    pp[2] = make_float4(fA[4], fB[4], fA[5], fB[5]);
    pp[3] = make_float4(2.0f * fA[6] - 1.0f, 2.0f * fB[6] - 1.0f,
                        1.0f - fA[6],        1.0f - fB[6]);
}

// ---------------------------------------------------------------------------
// Main: block = (image n, tri-tile (i,j), q-chunk qc). Thread owns one p-pair
// (f32x2-packed); q-chunk (64 q's, 4KB) in smem with duplicated components.
// ---------------------------------------------------------------------------
__global__ void __launch_bounds__(THREADS, 6)
crf_main(float* __restrict__ out) {
    __shared__ u64 sq[QC * 8];   // 64 q x 64B = 4KB

    int blk = blockIdx.x;
    int qc = blk & (QSPLIT - 1);
    int t  = (blk >> 3) % NTRI;
    int n  = blk / (NTRI * QSPLIT);
    int i = 0;
    {
        int rem = t;
        while (rem >= NT - i) { rem -= NT - i; i++; }
        t = i + rem;   // j
    }
    int j = t;
    int tid = threadIdx.x;

    // q-chunk copy: 512 u64, 2 per thread.
    {
        const u64* src = &g_qrec[(size_t)(n * P + j * TS + qc * QC) * 8];
        sq[tid]           = src[tid];
        sq[tid + THREADS] = src[tid + THREADS];
    }

    // p-pair record -> registers.
    u64 px0, px1, px2, px3, px4, hp, apb, bpb, acc0, acc1;
    {
        const ulonglong2* pp = reinterpret_cast<const ulonglong2*>(
            &g_prec[(size_t)(n * (P / 2) + i * (TS / 2) + tid) * 8]);
        ulonglong2 v0 = pp[0], v1 = pp[1], v2 = pp[2], v3 = pp[3];
        px0 = v0.x; px1 = v0.y; px2 = v1.x; px3 = v1.y; px4 = v2.x;
        hp = v2.y; apb = v3.x; bpb = v3.y;
        acc0 = 0ull; acc1 = 0ull;
    }
    __syncthreads();

    #pragma unroll 8
    for (int jq = 0; jq < QC; jq++) {
        const ulonglong2* qd = reinterpret_cast<const ulonglong2*>(&sq[jq * 8]);
        ulonglong2 A = qd[0];   // {f0q dup, f1q dup}
        ulonglong2 B = qd[1];   // {f2q dup, f3q dup}
        ulonglong2 C = qd[2];   // {f4q dup, hq dup}
        ulonglong2 D = qd[3];   // {s0q dup, pad}
        u64 L = add2(hp, C.y);
        L = fma2(px0, A.x, L);
        L = fma2(px1, A.y, L);
        L = fma2(px2, B.x, L);
        L = fma2(px3, B.y, L);
        L = fma2(px4, C.x, L);
        float2 Lf = unpack2(L);
        u64 k2 = pack2(ex2f(Lf.x), ex2f(Lf.y));
        acc1 = fma2(k2, D.x, acc1);   // sum over q of k * s0q   (per p half)
        acc0 = add2(k2, acc0);        // sum over q of k         (per p half)
    }

    // epilogue: a⊙acc1 + b⊙acc0, horizontal add over the p-pair.
    u64 r2 = mul2(apb, acc1);
    r2 = fma2(bpb, acc0, r2);
    float2 rf = unpack2(r2);
    float a = rf.x + rf.y;
    if (i != j) a *= 2.0f;   // symmetry weight

    // Deterministic block reduction.
    __shared__ float red[THREADS / 32];
    #pragma unroll
    for (int o = 16; o; o >>= 1) a += __shfl_down_sync(0xffffffffu, a, o);
    if ((tid & 31) == 0) red[tid >> 5] = a;
    __syncthreads();
    __shared__ bool is_last;
    if (tid == 0) {
        float v = 0.0f;
        #pragma unroll
        for (int w = 0; w < THREADS / 32; w++) v += red[w];
        g_partial[blk] = v;
        __threadfence();
        unsigned int c = atomicAdd(&g_count, 1u);
        is_last = (c == NBLOCKS - 1);
    }
    __syncthreads();

    // Last block: deterministic fixed-order final reduction + counter reset.
    if (is_last) {
        __threadfence();
        if (tid < 32) {
            float v = 0.0f;
            for (int k = tid; k < NBLOCKS; k += 32) v += g_partial[k];
            #pragma unroll
            for (int o = 16; o; o >>= 1) v += __shfl_down_sync(0xffffffffu, v, o);
            if (tid == 0) {
                out[0] = -(2e-9f / (float)N_IMG) * v;   // WEIGHT * (-sum / N)
                g_count = 0;                             // reset for next replay
            }
        }
    }
}

extern "C" void kernel_launch(void* const* d_in, const int* in_sizes, int n_in,
                              void* d_out, int out_size) {
    const float* images = (const float*)d_in[0];
    const float* segs   = (const float*)d_in[1];
    float* out = (float*)d_out;

    crf_prep<<<(N_IMG * (P / 2) + 255) / 256, 256>>>(images, segs);
    crf_main<<<NBLOCKS, THREADS>>>(out);
}